// round 5
// baseline (speedup 1.0000x reference)
#include <cuda_runtime.h>
#include <math.h>

// Problem constants (B=4, S=4096, D=2048, E=8, K=2)
#define NTOK    16384
#define DIM     2048
#define NEXP    8
#define NASSIGN (NTOK*2)       // 32768
#define CAP     5120           // int(NTOK*2/8 * 1.25)
#define TOKPB   32             // tokens per block
#define NBLK    (NTOK/TOKPB)   // 512 blocks
#define STAGES  3
#define CHUNK   128            // dims per pipeline stage
#define NSTAGE  (DIM/CHUNK)    // 16 stages
#define STAGE_BYTES (TOKPB*CHUNK*4)          // 16 KB
#define W_BYTES (NEXP*DIM*4)                 // 64 KB
#define SMEM_DYN (W_BYTES + STAGES*STAGE_BYTES)  // 112 KB

// Output layout (float32): [0,32768) indices | [32768,65536) weights |
// [65536] loss | [65537,98305) mask

// Scratch: __device__ globals (zero-init at load; last block resets so every
// graph replay sees zeros).
__device__ int      g_cnt[NEXP];
__device__ float    g_probsum[NEXP];
__device__ unsigned g_done;
__device__ unsigned long long g_bucket[NEXP][NASSIGN];

__device__ __forceinline__ void ffma2(unsigned long long& d,
                                      unsigned long long a,
                                      unsigned long long b) {
    asm("fma.rn.f32x2 %0, %1, %2, %0;" : "+l"(d) : "l"(a), "l"(b));
}
__device__ __forceinline__ float unpack_sum(unsigned long long v) {
    unsigned lo, hi;
    asm("mov.b64 {%0, %1}, %2;" : "=r"(lo), "=r"(hi) : "l"(v));
    return __uint_as_float(lo) + __uint_as_float(hi);
}
__device__ __forceinline__ unsigned smem_u32(const void* p) {
    return (unsigned)__cvta_generic_to_shared(p);
}
__device__ __forceinline__ void cp_async16(unsigned dst, const void* src) {
    asm volatile("cp.async.cg.shared.global [%0], [%1], 16;"
                 :: "r"(dst), "l"(src));
}

// One fused kernel: cp.async-pipelined GEMV + softmax + top-2 + renorm +
// stats; the LAST arriving block computes loss + (rare) capacity drop and
// resets scratch for the next graph replay.
__global__ __launch_bounds__(256, 2)
void router_main(const float* __restrict__ x,
                 const float* __restrict__ wg,
                 float* __restrict__ out) {
    extern __shared__ float smem[];
    float* sw = smem;                                   // w: 64 KB
    char*  sx = (char*)(smem + NEXP * DIM);             // x stages: 3 x 16 KB
    __shared__ float s_prob[NEXP];
    __shared__ int   s_last;

    const int tid  = threadIdx.x;
    const int warp = tid >> 5;
    const int lane = tid & 31;
    if (tid < NEXP) s_prob[tid] = 0.0f;

    // stage w_gate into shared (one-time; L2-resident after first wave)
    {
        float4* sw4 = (float4*)sw;
        const float4* wg4 = (const float4*)wg;
        #pragma unroll
        for (int i = tid; i < NEXP * DIM / 4; i += 256) sw4[i] = wg4[i];
    }

    const int tblock = blockIdx.x * TOKPB;
    const unsigned sx_base = smem_u32(sx);
    const char* xg = (const char*)x + (size_t)tblock * DIM * 4;

    // copy roles: 8 threads per token, 4 x 16B slots each (512B/token/stage)
    const int ctok  = tid >> 3;          // 0..31 (local token)
    const int cslot = tid & 7;           // 0..7
    const char* csrc_row = xg + (size_t)ctok * (DIM * 4) + cslot * 16;
    const unsigned cdst_row = sx_base + ctok * (CHUNK * 4) + cslot * 16;

    // prefill pipeline: stages 0..STAGES-1
    #pragma unroll
    for (int s = 0; s < STAGES; s++) {
        unsigned dst = cdst_row + s * STAGE_BYTES;
        const char* src = csrc_row + s * (CHUNK * 4);
        #pragma unroll
        for (int j = 0; j < 4; j++) cp_async16(dst + j * 128, src + j * 128);
        asm volatile("cp.async.commit_group;");
    }

    unsigned long long acc[4][NEXP];
    #pragma unroll
    for (int t = 0; t < 4; t++)
        #pragma unroll
        for (int e = 0; e < NEXP; e++) acc[t][e] = 0ull;

    const ulonglong2* sw2 = (const ulonglong2*)sw;

    for (int s = 0; s < NSTAGE; s++) {
        asm volatile("cp.async.wait_group %0;" :: "n"(STAGES - 1));
        __syncthreads();

        const int buf = s % STAGES;
        const ulonglong2* xs = (const ulonglong2*)(sx + buf * STAGE_BYTES);
        // x: lane reads 16B of token (warp*4+t); conflict-free
        ulonglong2 xv[4];
        #pragma unroll
        for (int t = 0; t < 4; t++) xv[t] = xs[(warp * 4 + t) * 32 + lane];
        #pragma unroll
        for (int e = 0; e < NEXP; e++) {
            ulonglong2 wv = sw2[e * (DIM / 4) + s * (CHUNK / 4) + lane];
            ffma2(acc[0][e], xv[0].x, wv.x); ffma2(acc[0][e], xv[0].y, wv.y);
            ffma2(acc[1][e], xv[1].x, wv.x); ffma2(acc[1][e], xv[1].y, wv.y);
            ffma2(acc[2][e], xv[2].x, wv.x); ffma2(acc[2][e], xv[2].y, wv.y);
            ffma2(acc[3][e], xv[3].x, wv.x); ffma2(acc[3][e], xv[3].y, wv.y);
        }
        __syncthreads();   // all reads of buf done before refill

        if (s + STAGES < NSTAGE) {
            unsigned dst = cdst_row + buf * STAGE_BYTES;
            const char* src = csrc_row + (s + STAGES) * (CHUNK * 4);
            #pragma unroll
            for (int j = 0; j < 4; j++) cp_async16(dst + j * 128, src + j * 128);
        }
        asm volatile("cp.async.commit_group;");  // empty group OK, keeps count
    }

    // Collapse f32x2 halves, butterfly so lanes 0-3 hold full logits.
    const int tbase = tblock + warp * 4;
    float logit[4][NEXP];
    #pragma unroll
    for (int t = 0; t < 4; t++)
        #pragma unroll
        for (int e = 0; e < NEXP; e++) {
            float v = unpack_sum(acc[t][e]);
            v += __shfl_xor_sync(0xffffffffu, v, 16);
            v += __shfl_xor_sync(0xffffffffu, v, 8);
            v += __shfl_xor_sync(0xffffffffu, v, 4);
            v += __shfl_xor_sync(0xffffffffu, v, 2);
            v += __shfl_xor_sync(0xffffffffu, v, 1);
            logit[t][e] = v;
        }

    if (lane < 4) {
        int token = tbase + lane;
        float p[NEXP];
        float m = logit[lane][0];
        #pragma unroll
        for (int e = 1; e < NEXP; e++) m = fmaxf(m, logit[lane][e]);
        float s = 0.0f;
        #pragma unroll
        for (int e = 0; e < NEXP; e++) { p[e] = expf(logit[lane][e] - m); s += p[e]; }
        float inv = 1.0f / s;
        #pragma unroll
        for (int e = 0; e < NEXP; e++) p[e] *= inv;

        // top-2, ties -> lowest index
        int i1 = 0; float b1 = p[0];
        #pragma unroll
        for (int e = 1; e < NEXP; e++) if (p[e] > b1) { b1 = p[e]; i1 = e; }
        int i2 = -1; float b2 = -1.0f;
        #pragma unroll
        for (int e = 0; e < NEXP; e++) if (e != i1 && p[e] > b2) { b2 = p[e]; i2 = e; }

        float ssum = b1 + b2;
        float w1 = b1 / ssum, w2 = b2 / ssum;

        int n0 = token * 2;
        out[n0]     = (float)i1;
        out[n0 + 1] = (float)i2;
        out[NASSIGN + n0]     = w1;
        out[NASSIGN + n0 + 1] = w2;
        out[2 * NASSIGN + 1 + n0]     = 1.0f;
        out[2 * NASSIGN + 1 + n0 + 1] = 1.0f;

        // per-expert bucket append; key = (weight desc, flat idx asc)
        int s1 = atomicAdd(&g_cnt[i1], 1);
        g_bucket[i1][s1] = ((unsigned long long)__float_as_uint(w1) << 32) |
                           (unsigned)(~(unsigned)n0);
        int s2 = atomicAdd(&g_cnt[i2], 1);
        g_bucket[i2][s2] = ((unsigned long long)__float_as_uint(w2) << 32) |
                           (unsigned)(~(unsigned)(n0 + 1));

        #pragma unroll
        for (int e = 0; e < NEXP; e++) atomicAdd(&s_prob[e], p[e]);
    }
    __syncthreads();
    if (tid < NEXP) atomicAdd(&g_probsum[tid], s_prob[tid]);
    __syncthreads();

    // ---- arrival counter: last block finalizes ----
    if (tid == 0) {
        __threadfence();
        unsigned old = atomicAdd(&g_done, 1u);
        s_last = (old == (unsigned)(gridDim.x - 1)) ? 1 : 0;
    }
    __syncthreads();
    if (!s_last) return;

    __shared__ int cnt[NEXP];
    if (tid < NEXP) cnt[tid] = __ldcg(&g_cnt[tid]);
    __syncthreads();

    if (tid == 0) {
        float imp[NEXP], imps = 0.0f;
        #pragma unroll
        for (int e = 0; e < NEXP; e++) { imp[e] = __ldcg(&g_probsum[e]); imps += imp[e]; }
        float loss = 0.0f;
        #pragma unroll
        for (int e = 0; e < NEXP; e++)
            loss += (imp[e] / imps) * ((float)cnt[e] / (float)NASSIGN);
        out[2 * NASSIGN] = (float)NEXP * loss;
    }

    // Capacity drop (rank = #{j: key > key_i}; keep iff rank < CAP). Matches
    // lexsort((-w, expert)) with flat-index tiebreak; rarely triggers.
    for (int e = 0; e < NEXP; e++) {
        int c = cnt[e];
        if (c <= CAP) continue;
        for (int i = tid; i < c; i += blockDim.x) {
            unsigned long long ki = __ldcg(&g_bucket[e][i]);
            int rank = 0;
            for (int j = 0; j < c; j++)
                rank += (__ldcg(&g_bucket[e][j]) > ki) ? 1 : 0;
            if (rank >= CAP) {
                unsigned n = ~(unsigned)(ki & 0xffffffffull);
                out[2 * NASSIGN + 1 + n] = 0.0f;
            }
        }
    }
    __syncthreads();

    if (tid < NEXP) { g_cnt[tid] = 0; g_probsum[tid] = 0.0f; }
    if (tid == 0)   { g_done = 0u; __threadfence(); }
}

extern "C" void kernel_launch(void* const* d_in, const int* in_sizes, int n_in,
                              void* d_out, int out_size) {
    const float* x  = (const float*)d_in[0];
    const float* wg = (const float*)d_in[1];
    float* out = (float*)d_out;
    (void)in_sizes; (void)n_in; (void)out_size;

    cudaFuncSetAttribute(router_main, cudaFuncAttributeMaxDynamicSharedMemorySize,
                         SMEM_DYN);

    router_main<<<NBLK, 256, SMEM_DYN>>>(x, wg, out);
}

// round 6
// speedup vs baseline: 1.0735x; 1.0735x over previous
#include <cuda_runtime.h>
#include <math.h>

// Problem constants (B=4, S=4096, D=2048, E=8, K=2)
#define NTOK    16384
#define DIM     2048
#define NEXP    8
#define NPAIR   4              // expert pairs (2 experts per f32x2 accumulator)
#define NASSIGN (NTOK*2)       // 32768
#define CAP     5120           // int(NTOK*2/8 * 1.25)
#define TOKPB   32
#define NBLK    (NTOK/TOKPB)   // 512
#define W_BYTES (NEXP*DIM*4)   // 64 KB (pair-interleaved w)

// Output layout (float32): [0,32768) indices | [32768,65536) weights |
// [65536] loss | [65537,98305) mask

// Scratch: __device__ globals (zero-init at load; last block resets so every
// graph replay sees zeros).
__device__ int      g_cnt[NEXP];
__device__ float    g_probsum[NEXP];
__device__ unsigned g_done;
__device__ unsigned long long g_bucket[NEXP][NASSIGN];

// Packed fp32x2 ops (Blackwell)
__device__ __forceinline__ void ffma2(unsigned long long& d,
                                      unsigned long long a,
                                      unsigned long long b) {
    asm("fma.rn.f32x2 %0, %1, %2, %0;" : "+l"(d) : "l"(a), "l"(b));
}
__device__ __forceinline__ unsigned long long add2(unsigned long long a,
                                                   unsigned long long b) {
    unsigned long long r;
    asm("add.rn.f32x2 %0, %1, %2;" : "=l"(r) : "l"(a), "l"(b));
    return r;
}
__device__ __forceinline__ unsigned long long dup2(float a) {
    unsigned long long r;
    asm("mov.b64 %0, {%1, %1};" : "=l"(r) : "f"(a));
    return r;
}
__device__ __forceinline__ void unpack2(unsigned long long v, float& lo, float& hi) {
    unsigned a, b;
    asm("mov.b64 {%0, %1}, %2;" : "=r"(a), "=r"(b) : "l"(v));
    lo = __uint_as_float(a); hi = __uint_as_float(b);
}

// One fused kernel. w staged into smem pair-interleaved:
//   slot(p, i, s, lane) @ byte p*16384 + i*1024 + s*512 + lane*16   (16 B)
//   holds dims d0 = i*128 + lane*4 + 2s, d0+1 for experts 2p,2p+1:
//   (w[2p][d0], w[2p+1][d0], w[2p][d0+1], w[2p+1][d0+1])
// Consumption: lane stride 16 B -> conflict-free LDS.128.
__global__ __launch_bounds__(256, 3)
void router_main(const float* __restrict__ x,
                 const float* __restrict__ wg,
                 float* __restrict__ out) {
    extern __shared__ float sw[];              // 64 KB pair-interleaved w
    __shared__ float s_prob[NEXP];
    __shared__ int   s_last;

    const int tid  = threadIdx.x;
    const int warp = tid >> 5;
    const int lane = tid & 31;
    if (tid < NEXP) s_prob[tid] = 0.0f;

    // ---- stage w pair-interleaved (one-time; wg L2-resident after wave 1)
    {
        const float4* wg4 = (const float4*)wg;
        #pragma unroll
        for (int k = 0; k < 8; k++) {
            int t = tid + k * 256;             // 2048 tasks
            int p = t >> 9;                    // 0..3
            int c = t & 511;                   // 0..511: i = c>>5, l = c&31
            int i = c >> 5, l = c & 31;
            float4 A = wg4[(2 * p) * 512 + c];       // expert 2p,   dims 4c..4c+3
            float4 Bv = wg4[(2 * p + 1) * 512 + c];  // expert 2p+1
            char* base = (char*)sw + p * 16384 + i * 1024 + l * 16;
            *(float4*)(base)       = make_float4(A.x, Bv.x, A.y, Bv.y); // s=0
            *(float4*)(base + 512) = make_float4(A.z, Bv.z, A.w, Bv.w); // s=1
        }
    }
    __syncthreads();

    const int tblock = blockIdx.x * TOKPB;
    const int tbase  = tblock + warp * 4;
    const float4* xr0 = (const float4*)(x + (size_t)(tbase + 0) * DIM);
    const float4* xr1 = (const float4*)(x + (size_t)(tbase + 1) * DIM);
    const float4* xr2 = (const float4*)(x + (size_t)(tbase + 2) * DIM);
    const float4* xr3 = (const float4*)(x + (size_t)(tbase + 3) * DIM);

    unsigned long long acc[4][NPAIR];
    #pragma unroll
    for (int t = 0; t < 4; t++)
        #pragma unroll
        for (int p = 0; p < NPAIR; p++) acc[t][p] = 0ull;

    #pragma unroll 1
    for (int i = 0; i < 16; i++) {
        int c = i * 32 + lane;
        float4 x0 = xr0[c];
        float4 x1 = xr1[c];
        float4 x2 = xr2[c];
        float4 x3 = xr3[c];

        // lane-duplicated x operands (alu pipe; reused across all 4 pairs)
        unsigned long long d0a = dup2(x0.x), d0b = dup2(x0.y), d0c = dup2(x0.z), d0d = dup2(x0.w);
        unsigned long long d1a = dup2(x1.x), d1b = dup2(x1.y), d1c = dup2(x1.z), d1d = dup2(x1.w);
        unsigned long long d2a = dup2(x2.x), d2b = dup2(x2.y), d2c = dup2(x2.z), d2d = dup2(x2.w);
        unsigned long long d3a = dup2(x3.x), d3b = dup2(x3.y), d3c = dup2(x3.z), d3d = dup2(x3.w);

        const char* wb = (const char*)sw + i * 1024 + lane * 16;
        #pragma unroll
        for (int p = 0; p < NPAIR; p++) {
            ulonglong2 wa = *(const ulonglong2*)(wb + p * 16384);        // dims +0,+1
            ulonglong2 wc = *(const ulonglong2*)(wb + p * 16384 + 512);  // dims +2,+3
            ffma2(acc[0][p], d0a, wa.x); ffma2(acc[0][p], d0b, wa.y);
            ffma2(acc[0][p], d0c, wc.x); ffma2(acc[0][p], d0d, wc.y);
            ffma2(acc[1][p], d1a, wa.x); ffma2(acc[1][p], d1b, wa.y);
            ffma2(acc[1][p], d1c, wc.x); ffma2(acc[1][p], d1d, wc.y);
            ffma2(acc[2][p], d2a, wa.x); ffma2(acc[2][p], d2b, wa.y);
            ffma2(acc[2][p], d2c, wc.x); ffma2(acc[2][p], d2d, wc.y);
            ffma2(acc[3][p], d3a, wa.x); ffma2(acc[3][p], d3b, wa.y);
            ffma2(acc[3][p], d3c, wc.x); ffma2(acc[3][p], d3d, wc.y);
        }
    }

    // Packed butterfly reduce: every lane ends with full (e2p, e2p+1) sums.
    #pragma unroll
    for (int t = 0; t < 4; t++)
        #pragma unroll
        for (int p = 0; p < NPAIR; p++) {
            unsigned long long v = acc[t][p];
            v = add2(v, __shfl_xor_sync(0xffffffffu, v, 16));
            v = add2(v, __shfl_xor_sync(0xffffffffu, v, 8));
            v = add2(v, __shfl_xor_sync(0xffffffffu, v, 4));
            v = add2(v, __shfl_xor_sync(0xffffffffu, v, 2));
            v = add2(v, __shfl_xor_sync(0xffffffffu, v, 1));
            acc[t][p] = v;
        }

    if (lane < 4) {
        int token = tbase + lane;
        float lg[NEXP];
        #pragma unroll
        for (int t = 0; t < 4; t++)
            if (lane == t) {
                #pragma unroll
                for (int p = 0; p < NPAIR; p++)
                    unpack2(acc[t][p], lg[2 * p], lg[2 * p + 1]);
            }

        float pr[NEXP];
        float m = lg[0];
        #pragma unroll
        for (int e = 1; e < NEXP; e++) m = fmaxf(m, lg[e]);
        float s = 0.0f;
        #pragma unroll
        for (int e = 0; e < NEXP; e++) { pr[e] = expf(lg[e] - m); s += pr[e]; }
        float inv = 1.0f / s;
        #pragma unroll
        for (int e = 0; e < NEXP; e++) pr[e] *= inv;

        // top-2, ties -> lowest index
        int i1 = 0; float b1 = pr[0];
        #pragma unroll
        for (int e = 1; e < NEXP; e++) if (pr[e] > b1) { b1 = pr[e]; i1 = e; }
        int i2 = -1; float b2 = -1.0f;
        #pragma unroll
        for (int e = 0; e < NEXP; e++) if (e != i1 && pr[e] > b2) { b2 = pr[e]; i2 = e; }

        float ssum = b1 + b2;
        float w1 = b1 / ssum, w2 = b2 / ssum;

        int n0 = token * 2;
        out[n0]     = (float)i1;
        out[n0 + 1] = (float)i2;
        out[NASSIGN + n0]     = w1;
        out[NASSIGN + n0 + 1] = w2;
        out[2 * NASSIGN + 1 + n0]     = 1.0f;
        out[2 * NASSIGN + 1 + n0 + 1] = 1.0f;

        // per-expert bucket append; key = (weight desc, flat idx asc)
        int s1 = atomicAdd(&g_cnt[i1], 1);
        g_bucket[i1][s1] = ((unsigned long long)__float_as_uint(w1) << 32) |
                           (unsigned)(~(unsigned)n0);
        int s2 = atomicAdd(&g_cnt[i2], 1);
        g_bucket[i2][s2] = ((unsigned long long)__float_as_uint(w2) << 32) |
                           (unsigned)(~(unsigned)(n0 + 1));

        #pragma unroll
        for (int e = 0; e < NEXP; e++) atomicAdd(&s_prob[e], pr[e]);
    }
    __syncthreads();
    if (tid < NEXP) atomicAdd(&g_probsum[tid], s_prob[tid]);
    __syncthreads();

    // ---- arrival counter: last block finalizes ----
    if (tid == 0) {
        __threadfence();
        unsigned old = atomicAdd(&g_done, 1u);
        s_last = (old == (unsigned)(gridDim.x - 1)) ? 1 : 0;
    }
    __syncthreads();
    if (!s_last) return;

    __shared__ int cnt[NEXP];
    if (tid < NEXP) cnt[tid] = __ldcg(&g_cnt[tid]);
    __syncthreads();

    if (tid == 0) {
        float imp[NEXP], imps = 0.0f;
        #pragma unroll
        for (int e = 0; e < NEXP; e++) { imp[e] = __ldcg(&g_probsum[e]); imps += imp[e]; }
        float loss = 0.0f;
        #pragma unroll
        for (int e = 0; e < NEXP; e++)
            loss += (imp[e] / imps) * ((float)cnt[e] / (float)NASSIGN);
        out[2 * NASSIGN] = (float)NEXP * loss;
    }

    // Capacity drop (rank = #{j: key > key_i}; keep iff rank < CAP). Matches
    // lexsort((-w, expert)) with flat-index tiebreak; rarely triggers.
    for (int e = 0; e < NEXP; e++) {
        int c = cnt[e];
        if (c <= CAP) continue;
        for (int i = tid; i < c; i += blockDim.x) {
            unsigned long long ki = __ldcg(&g_bucket[e][i]);
            int rank = 0;
            for (int j = 0; j < c; j++)
                rank += (__ldcg(&g_bucket[e][j]) > ki) ? 1 : 0;
            if (rank >= CAP) {
                unsigned n = ~(unsigned)(ki & 0xffffffffull);
                out[2 * NASSIGN + 1 + n] = 0.0f;
            }
        }
    }
    __syncthreads();

    if (tid < NEXP) { g_cnt[tid] = 0; g_probsum[tid] = 0.0f; }
    if (tid == 0)   { g_done = 0u; __threadfence(); }
}

extern "C" void kernel_launch(void* const* d_in, const int* in_sizes, int n_in,
                              void* d_out, int out_size) {
    const float* x  = (const float*)d_in[0];
    const float* wg = (const float*)d_in[1];
    float* out = (float*)d_out;
    (void)in_sizes; (void)n_in; (void)out_size;

    cudaFuncSetAttribute(router_main, cudaFuncAttributeMaxDynamicSharedMemorySize,
                         W_BYTES);

    router_main<<<NBLK, 256, W_BYTES>>>(x, wg, out);
}

// round 7
// speedup vs baseline: 1.2334x; 1.1489x over previous
#include <cuda_runtime.h>
#include <math.h>

// Problem constants (B=4, S=4096, D=2048, E=8, K=2)
#define NTOK    16384
#define DIM     2048
#define NEXP    8
#define NASSIGN (NTOK*2)       // 32768
#define CAP     5120           // int(NTOK*2/8 * 1.25)
#define TOKPB   32
#define NBLK    (NTOK/TOKPB)   // 512
#define W_BYTES (NEXP*DIM*4)   // 64 KB

// Output layout (float32): [0,32768) indices | [32768,65536) weights |
// [65536] loss | [65537,98305) mask

// Scratch: __device__ globals (zero-init at load; last block resets so every
// graph replay sees zeros).
__device__ int      g_cnt[NEXP];
__device__ float    g_probsum[NEXP];
__device__ unsigned g_done;
__device__ unsigned long long g_bucket[NEXP][NASSIGN];

// Packed fp32x2 FMA (Blackwell): d = a*b + d on two f32 lanes (dim pairs).
__device__ __forceinline__ void ffma2(unsigned long long& d,
                                      unsigned long long a,
                                      unsigned long long b) {
    asm("fma.rn.f32x2 %0, %1, %2, %0;" : "+l"(d) : "l"(a), "l"(b));
}
__device__ __forceinline__ float unpack_sum(unsigned long long v) {
    unsigned lo, hi;
    asm("mov.b64 {%0, %1}, %2;" : "=r"(lo), "=r"(hi) : "l"(v));
    return __uint_as_float(lo) + __uint_as_float(hi);
}

// One fused kernel: GEMV (R3-proven loop) + softmax + top-2 + renorm + stats;
// LAST arriving block computes loss + (rare) capacity drop + resets scratch.
__global__ __launch_bounds__(256, 2)
void router_main(const float* __restrict__ x,
                 const float* __restrict__ wg,
                 float* __restrict__ out) {
    extern __shared__ float sw[];              // 8*2048 f32 = 64 KB
    __shared__ float s_prob[NEXP];
    __shared__ int   s_cnt[NEXP];              // block-local expert counts
    __shared__ int   s_base[NEXP];             // reserved global base per expert
    __shared__ int   s_last;

    const int tid  = threadIdx.x;
    const int warp = tid >> 5;
    const int lane = tid & 31;
    if (tid < NEXP) { s_prob[tid] = 0.0f; s_cnt[tid] = 0; }

    // stage w_gate into shared (one-time; L2-resident after first wave)
    {
        float4* sw4 = (float4*)sw;
        const float4* wg4 = (const float4*)wg;
        #pragma unroll
        for (int i = tid; i < NEXP * DIM / 4; i += 256) sw4[i] = wg4[i];
    }
    __syncthreads();

    const int tbase = (blockIdx.x * 8 + warp) * 4;

    const ulonglong2* xr0 = (const ulonglong2*)(x + (size_t)(tbase + 0) * DIM);
    const ulonglong2* xr1 = (const ulonglong2*)(x + (size_t)(tbase + 1) * DIM);
    const ulonglong2* xr2 = (const ulonglong2*)(x + (size_t)(tbase + 2) * DIM);
    const ulonglong2* xr3 = (const ulonglong2*)(x + (size_t)(tbase + 3) * DIM);
    const ulonglong2* sw2 = (const ulonglong2*)sw;

    unsigned long long acc[4][NEXP];
    #pragma unroll
    for (int t = 0; t < 4; t++)
        #pragma unroll
        for (int e = 0; e < NEXP; e++) acc[t][e] = 0ull;

    // R3-proven loop: unroll 2, plain loads; ptxas front-batches 8 LDG.128.
    #pragma unroll 2
    for (int i = 0; i < 16; i++) {
        int c = i * 32 + lane;
        ulonglong2 x0 = xr0[c];
        ulonglong2 x1 = xr1[c];
        ulonglong2 x2 = xr2[c];
        ulonglong2 x3 = xr3[c];
        #pragma unroll
        for (int e = 0; e < NEXP; e++) {
            ulonglong2 wv = sw2[e * (DIM / 4) + c];
            ffma2(acc[0][e], x0.x, wv.x); ffma2(acc[0][e], x0.y, wv.y);
            ffma2(acc[1][e], x1.x, wv.x); ffma2(acc[1][e], x1.y, wv.y);
            ffma2(acc[2][e], x2.x, wv.x); ffma2(acc[2][e], x2.y, wv.y);
            ffma2(acc[3][e], x3.x, wv.x); ffma2(acc[3][e], x3.y, wv.y);
        }
    }

    // Collapse f32x2 halves, butterfly so lanes 0-3 hold full logits.
    float logit[4][NEXP];
    #pragma unroll
    for (int t = 0; t < 4; t++)
        #pragma unroll
        for (int e = 0; e < NEXP; e++) {
            float v = unpack_sum(acc[t][e]);
            v += __shfl_xor_sync(0xffffffffu, v, 16);
            v += __shfl_xor_sync(0xffffffffu, v, 8);
            v += __shfl_xor_sync(0xffffffffu, v, 4);
            v += __shfl_xor_sync(0xffffffffu, v, 2);
            v += __shfl_xor_sync(0xffffffffu, v, 1);
            logit[t][e] = v;
        }

    // Per-token epilogue on lanes 0-3; bucket slots reserved block-locally.
    int i1 = 0, i2 = 0, r1 = 0, r2 = 0, n0 = 0;
    unsigned long long key1 = 0, key2 = 0;
    bool active = (lane < 4);
    if (active) {
        int token = tbase + lane;
        float p[NEXP];
        float m = logit[lane][0];
        #pragma unroll
        for (int e = 1; e < NEXP; e++) m = fmaxf(m, logit[lane][e]);
        float s = 0.0f;
        #pragma unroll
        for (int e = 0; e < NEXP; e++) { p[e] = expf(logit[lane][e] - m); s += p[e]; }
        float inv = 1.0f / s;
        #pragma unroll
        for (int e = 0; e < NEXP; e++) p[e] *= inv;

        // top-2, ties -> lowest index
        float b1 = p[0];
        #pragma unroll
        for (int e = 1; e < NEXP; e++) if (p[e] > b1) { b1 = p[e]; i1 = e; }
        i2 = -1; float b2 = -1.0f;
        #pragma unroll
        for (int e = 0; e < NEXP; e++) if (e != i1 && p[e] > b2) { b2 = p[e]; i2 = e; }

        float ssum = b1 + b2;
        float w1 = b1 / ssum, w2 = b2 / ssum;

        n0 = token * 2;
        out[n0]     = (float)i1;
        out[n0 + 1] = (float)i2;
        out[NASSIGN + n0]     = w1;
        out[NASSIGN + n0 + 1] = w2;
        out[2 * NASSIGN + 1 + n0]     = 1.0f;
        out[2 * NASSIGN + 1 + n0 + 1] = 1.0f;

        // order-independent keys: (weight desc via bits, flat idx asc via ~n)
        key1 = ((unsigned long long)__float_as_uint(w1) << 32) |
               (unsigned)(~(unsigned)n0);
        key2 = ((unsigned long long)__float_as_uint(w2) << 32) |
               (unsigned)(~(unsigned)(n0 + 1));
        r1 = atomicAdd(&s_cnt[i1], 1);          // smem slot reservation
        r2 = atomicAdd(&s_cnt[i2], 1);

        #pragma unroll
        for (int e = 0; e < NEXP; e++) atomicAdd(&s_prob[e], p[e]);
    }
    __syncthreads();

    // one global atomic per expert per block (8 instead of 64)
    if (tid < NEXP) {
        s_base[tid] = s_cnt[tid] ? atomicAdd(&g_cnt[tid], s_cnt[tid]) : 0;
        atomicAdd(&g_probsum[tid], s_prob[tid]);
    }
    __syncthreads();

    if (active) {
        g_bucket[i1][s_base[i1] + r1] = key1;
        g_bucket[i2][s_base[i2] + r2] = key2;
    }
    __syncthreads();

    // ---- arrival counter: last block finalizes ----
    if (tid == 0) {
        __threadfence();
        unsigned old = atomicAdd(&g_done, 1u);
        s_last = (old == (unsigned)(gridDim.x - 1)) ? 1 : 0;
    }
    __syncthreads();
    if (!s_last) return;

    __shared__ int cnt[NEXP];
    if (tid < NEXP) cnt[tid] = __ldcg(&g_cnt[tid]);
    __syncthreads();

    if (tid == 0) {
        float imp[NEXP], imps = 0.0f;
        #pragma unroll
        for (int e = 0; e < NEXP; e++) { imp[e] = __ldcg(&g_probsum[e]); imps += imp[e]; }
        float loss = 0.0f;
        #pragma unroll
        for (int e = 0; e < NEXP; e++)
            loss += (imp[e] / imps) * ((float)cnt[e] / (float)NASSIGN);
        out[2 * NASSIGN] = (float)NEXP * loss;
    }

    // Capacity drop (rank = #{j: key > key_i}; keep iff rank < CAP). Matches
    // lexsort((-w, expert)) with flat-index tiebreak; rarely triggers
    // (expected per-expert count ~4096 << 5120).
    for (int e = 0; e < NEXP; e++) {
        int c = cnt[e];
        if (c <= CAP) continue;
        for (int i = tid; i < c; i += blockDim.x) {
            unsigned long long ki = __ldcg(&g_bucket[e][i]);
            int rank = 0;
            for (int j = 0; j < c; j++)
                rank += (__ldcg(&g_bucket[e][j]) > ki) ? 1 : 0;
            if (rank >= CAP) {
                unsigned n = ~(unsigned)(ki & 0xffffffffull);
                out[2 * NASSIGN + 1 + n] = 0.0f;
            }
        }
    }
    __syncthreads();

    if (tid < NEXP) { g_cnt[tid] = 0; g_probsum[tid] = 0.0f; }
    if (tid == 0)   { g_done = 0u; __threadfence(); }
}

extern "C" void kernel_launch(void* const* d_in, const int* in_sizes, int n_in,
                              void* d_out, int out_size) {
    const float* x  = (const float*)d_in[0];
    const float* wg = (const float*)d_in[1];
    float* out = (float*)d_out;
    (void)in_sizes; (void)n_in; (void)out_size;

    cudaFuncSetAttribute(router_main, cudaFuncAttributeMaxDynamicSharedMemorySize,
                         W_BYTES);

    router_main<<<NBLK, 256, W_BYTES>>>(x, wg, out);
}